// round 2
// baseline (speedup 1.0000x reference)
#include <cuda_runtime.h>
#include <cuda_bf16.h>
#include <math.h>

// ---------------------------------------------------------------------------
// Problem dims (fixed by the dataset)
// ---------------------------------------------------------------------------
#define Bdim 2
#define Tdim 4096
#define Cdim 2048
#define HSZ  64
#define NHEAD (Cdim / HSZ)          // 32
#define Mrows (Bdim * Tdim)         // 8192
#define DW 128
#define DA 128
#define DV 64
#define DG 224

static const size_t BTC = (size_t)Bdim * Tdim * Cdim;   // 16,777,216

// ---------------------------------------------------------------------------
// Scratch (device globals — no allocations allowed)
// ---------------------------------------------------------------------------
__device__ float g_xr[Bdim * Tdim * Cdim];
__device__ float g_xw[Bdim * Tdim * Cdim];
__device__ float g_xk[Bdim * Tdim * Cdim];
__device__ float g_xv[Bdim * Tdim * Cdim];
__device__ float g_xa[Bdim * Tdim * Cdim];
__device__ float g_xg[Bdim * Tdim * Cdim];
__device__ float g_ko[Bdim * Tdim * Cdim];   // raw k gemm
__device__ float g_vg[Bdim * Tdim * Cdim];   // raw v gemm
__device__ float g_hw[Mrows * DW];
__device__ float g_ha[Mrows * DA];
__device__ float g_hv[Mrows * DV];
__device__ float g_hg[Mrows * DG];

// ---------------------------------------------------------------------------
// Kernel 1: time-shift + 6 mixes + v_first passthrough
// ---------------------------------------------------------------------------
__global__ __launch_bounds__(256) void mix_kernel(
    const float* __restrict__ x, const float* __restrict__ vf,
    const float* __restrict__ mr, const float* __restrict__ mw,
    const float* __restrict__ mk, const float* __restrict__ mv,
    const float* __restrict__ ma, const float* __restrict__ mg,
    float* __restrict__ out_vf)
{
    int idx = blockIdx.x * blockDim.x + threadIdx.x;
    if (idx >= (int)BTC) return;
    int c   = idx & (Cdim - 1);
    int row = idx >> 11;             // b*T + t
    int t   = row & (Tdim - 1);
    float xc = x[idx];
    float xp = (t == 0) ? 0.0f : x[idx - Cdim];
    float xx = xp - xc;
    g_xr[idx] = fmaf(xx, mr[c], xc);
    g_xw[idx] = fmaf(xx, mw[c], xc);
    g_xk[idx] = fmaf(xx, mk[c], xc);
    g_xv[idx] = fmaf(xx, mv[c], xc);
    g_xa[idx] = fmaf(xx, ma[c], xc);
    g_xg[idx] = fmaf(xx, mg[c], xc);
    out_vf[idx] = vf[idx];
}

// ---------------------------------------------------------------------------
// GEMM tiles
// ---------------------------------------------------------------------------
#define BM 128
#define BN 128
#define BK 16
#define TM 8
#define TN 8

// O[m,n] = sum_k A[m,k] * W[n,k]   (A: [M,K] row-major, W: [N,K] row-major)
// M % 128 == 0, N % 128 == 0, K % 16 == 0 (true for all call sites)
__global__ __launch_bounds__(256) void gemm_abT(
    const float* __restrict__ A, const float* __restrict__ W,
    float* __restrict__ O, int M, int N, int K)
{
    __shared__ float As[BK][BM];
    __shared__ float Bs[BK][BN];
    const int m0 = blockIdx.x * BM;
    const int n0 = blockIdx.y * BN;
    const int tid = threadIdx.x;
    const int lrow = tid >> 2;
    const int lk   = (tid & 3) * 4;
    const int tm = (tid >> 4) * TM;
    const int tn = (tid & 15) * TN;

    float acc[TM][TN] = {};
    for (int k0 = 0; k0 < K; k0 += BK) {
        #pragma unroll
        for (int p = 0; p < 2; p++) {
            int r = lrow + p * 64;
            float4 av = *(const float4*)&A[(size_t)(m0 + r) * K + k0 + lk];
            As[lk + 0][r] = av.x; As[lk + 1][r] = av.y;
            As[lk + 2][r] = av.z; As[lk + 3][r] = av.w;
            float4 bv = *(const float4*)&W[(size_t)(n0 + r) * K + k0 + lk];
            Bs[lk + 0][r] = bv.x; Bs[lk + 1][r] = bv.y;
            Bs[lk + 2][r] = bv.z; Bs[lk + 3][r] = bv.w;
        }
        __syncthreads();
        #pragma unroll
        for (int kk = 0; kk < BK; kk++) {
            float ra[TM], rb[TN];
            #pragma unroll
            for (int i = 0; i < TM; i += 4) *(float4*)&ra[i] = *(const float4*)&As[kk][tm + i];
            #pragma unroll
            for (int j = 0; j < TN; j += 4) *(float4*)&rb[j] = *(const float4*)&Bs[kk][tn + j];
            #pragma unroll
            for (int i = 0; i < TM; i++)
                #pragma unroll
                for (int j = 0; j < TN; j++)
                    acc[i][j] = fmaf(ra[i], rb[j], acc[i][j]);
        }
        __syncthreads();
    }
    #pragma unroll
    for (int i = 0; i < TM; i++) {
        float* orow = &O[(size_t)(m0 + tm + i) * N + n0 + tn];
        #pragma unroll
        for (int j = 0; j < TN; j += 4)
            *(float4*)&orow[j] = make_float4(acc[i][j], acc[i][j+1], acc[i][j+2], acc[i][j+3]);
    }
}

// Epilogue modes for gemm_ab
#define EPI_NONE 0
#define EPI_TANH 1
#define EPI_W    2
#define EPI_SIG  3
#define EPI_VMIX 4

__device__ __forceinline__ float sigmoidf_(float y) { return 1.0f / (1.0f + expf(-y)); }

// O[m,n] = epi( sum_k A[m,k] * B[k,n] )   (A: [M,K] row-major, B: [K,N] row-major)
// M % 128 == 0, K % 16 == 0, N % 32 == 0 (N may be < BN or not a multiple of BN)
template <int EPI>
__global__ __launch_bounds__(256) void gemm_ab(
    const float* __restrict__ A, const float* __restrict__ B,
    float* __restrict__ O, int M, int N, int K,
    const float* __restrict__ bias,
    const float* __restrict__ vg, const float* __restrict__ vf)
{
    __shared__ float As[BK][BM];
    __shared__ float Bs[BK][BN];
    const int m0 = blockIdx.x * BM;
    const int n0 = blockIdx.y * BN;
    const int tid = threadIdx.x;
    const int lrow = tid >> 2;
    const int lk   = (tid & 3) * 4;
    const int kr   = tid >> 5;          // 0..7
    const int nv   = (tid & 31) * 4;    // 0..124
    const int tm = (tid >> 4) * TM;
    const int tn = (tid & 15) * TN;

    float acc[TM][TN] = {};
    for (int k0 = 0; k0 < K; k0 += BK) {
        #pragma unroll
        for (int p = 0; p < 2; p++) {
            int r = lrow + p * 64;
            float4 av = *(const float4*)&A[(size_t)(m0 + r) * K + k0 + lk];
            As[lk + 0][r] = av.x; As[lk + 1][r] = av.y;
            As[lk + 2][r] = av.z; As[lk + 3][r] = av.w;
        }
        #pragma unroll
        for (int p = 0; p < 2; p++) {
            int krr = kr + p * 8;
            float4 bv = make_float4(0.f, 0.f, 0.f, 0.f);
            if (n0 + nv < N)   // N % 4 == 0 so float4 is all-in or all-out
                bv = *(const float4*)&B[(size_t)(k0 + krr) * N + n0 + nv];
            Bs[krr][nv + 0] = bv.x; Bs[krr][nv + 1] = bv.y;
            Bs[krr][nv + 2] = bv.z; Bs[krr][nv + 3] = bv.w;
        }
        __syncthreads();
        #pragma unroll
        for (int kk = 0; kk < BK; kk++) {
            float ra[TM], rb[TN];
            #pragma unroll
            for (int i = 0; i < TM; i += 4) *(float4*)&ra[i] = *(const float4*)&As[kk][tm + i];
            #pragma unroll
            for (int j = 0; j < TN; j += 4) *(float4*)&rb[j] = *(const float4*)&Bs[kk][tn + j];
            #pragma unroll
            for (int i = 0; i < TM; i++)
                #pragma unroll
                for (int j = 0; j < TN; j++)
                    acc[i][j] = fmaf(ra[i], rb[j], acc[i][j]);
        }
        __syncthreads();
    }

    #pragma unroll
    for (int i = 0; i < TM; i++) {
        int m = m0 + tm + i;
        #pragma unroll
        for (int j = 0; j < TN; j++) {
            int n = n0 + tn + j;
            if (n >= N) continue;
            float val = acc[i][j];
            float o;
            if (EPI == EPI_NONE) {
                o = val;
            } else if (EPI == EPI_TANH) {
                o = tanhf(val);
            } else if (EPI == EPI_W) {
                float y  = bias[n] + val;
                // softplus(-y) computed stably
                float sp = fmaxf(-y, 0.0f) + log1pf(expf(-fabsf(y)));
                o = -sp - 0.5f;
            } else if (EPI == EPI_SIG) {
                float y = val + (bias ? bias[n] : 0.0f);
                o = sigmoidf_(y);
            } else { // EPI_VMIX
                float s = sigmoidf_(bias[n] + val);
                size_t idx = (size_t)m * N + n;
                float vgv = vg[idx];
                o = vgv + (vf[idx] - vgv) * s;
            }
            O[(size_t)m * N + n] = o;
        }
    }
}

// ---------------------------------------------------------------------------
// Kernel: kk = headwise-normalize(k * k_k);  k_final = k * (1 + (a-1)*k_a)
// One warp per (row, head): 64 elements, 2 per lane.
// ---------------------------------------------------------------------------
__global__ __launch_bounds__(256) void kk_fin_kernel(
    const float* __restrict__ k_k, const float* __restrict__ k_a,
    const float* __restrict__ a_out,
    float* __restrict__ out_kk, float* __restrict__ out_k)
{
    int gw   = (blockIdx.x * blockDim.x + threadIdx.x) >> 5;
    int lane = threadIdx.x & 31;
    int row  = gw >> 5;           // 0..8191
    int h    = gw & 31;           // 0..31
    if (row >= Mrows) return;
    int base = row * Cdim + h * HSZ;
    int c0 = h * HSZ + lane, c1 = c0 + 32;

    float k0v = g_ko[base + lane];
    float k1v = g_ko[base + 32 + lane];
    float kk0 = k0v * k_k[c0];
    float kk1 = k1v * k_k[c1];
    float ss = kk0 * kk0 + kk1 * kk1;
    #pragma unroll
    for (int o = 16; o > 0; o >>= 1) ss += __shfl_xor_sync(0xFFFFFFFFu, ss, o);
    float inv = 1.0f / fmaxf(sqrtf(ss), 1e-12f);
    out_kk[base + lane]      = kk0 * inv;
    out_kk[base + 32 + lane] = kk1 * inv;

    float a0v = a_out[base + lane];
    float a1v = a_out[base + 32 + lane];
    out_k[base + lane]      = k0v * fmaf(a0v - 1.0f, k_a[c0], 1.0f);
    out_k[base + 32 + lane] = k1v * fmaf(a1v - 1.0f, k_a[c1], 1.0f);
}

// ---------------------------------------------------------------------------
// Launch
// ---------------------------------------------------------------------------
extern "C" void kernel_launch(void* const* d_in, const int* in_sizes, int n_in,
                              void* d_out, int out_size)
{
    const float* x   = (const float*)d_in[0];
    const float* vf  = (const float*)d_in[1];
    const float* x_r = (const float*)d_in[2];
    const float* x_w = (const float*)d_in[3];
    const float* x_k = (const float*)d_in[4];
    const float* x_v = (const float*)d_in[5];
    const float* x_a = (const float*)d_in[6];
    const float* x_g = (const float*)d_in[7];
    const float* w0  = (const float*)d_in[8];
    const float* w1  = (const float*)d_in[9];
    const float* w2  = (const float*)d_in[10];
    const float* a0  = (const float*)d_in[11];
    const float* a1  = (const float*)d_in[12];
    const float* a2  = (const float*)d_in[13];
    const float* v0  = (const float*)d_in[14];
    const float* v1  = (const float*)d_in[15];
    const float* v2  = (const float*)d_in[16];
    const float* g1  = (const float*)d_in[17];
    const float* g2  = (const float*)d_in[18];
    const float* k_k = (const float*)d_in[19];
    const float* k_a = (const float*)d_in[20];
    const float* Wr  = (const float*)d_in[21];
    const float* Wk  = (const float*)d_in[22];
    const float* Wv  = (const float*)d_in[23];
    (void)in_sizes; (void)n_in; (void)out_size;

    float* out = (float*)d_out;
    float* out_r  = out + 0 * BTC;
    float* out_w  = out + 1 * BTC;
    float* out_k  = out + 2 * BTC;
    float* out_v  = out + 3 * BTC;
    float* out_a  = out + 4 * BTC;
    float* out_g  = out + 5 * BTC;
    float* out_kk = out + 6 * BTC;
    float* out_vf = out + 7 * BTC;

    // scratch pointers
    float *p_xr, *p_xw, *p_xk, *p_xv, *p_xa, *p_xg, *p_ko, *p_vg, *p_hw, *p_ha, *p_hv, *p_hg;
    cudaGetSymbolAddress((void**)&p_xr, g_xr);
    cudaGetSymbolAddress((void**)&p_xw, g_xw);
    cudaGetSymbolAddress((void**)&p_xk, g_xk);
    cudaGetSymbolAddress((void**)&p_xv, g_xv);
    cudaGetSymbolAddress((void**)&p_xa, g_xa);
    cudaGetSymbolAddress((void**)&p_xg, g_xg);
    cudaGetSymbolAddress((void**)&p_ko, g_ko);
    cudaGetSymbolAddress((void**)&p_vg, g_vg);
    cudaGetSymbolAddress((void**)&p_hw, g_hw);
    cudaGetSymbolAddress((void**)&p_ha, g_ha);
    cudaGetSymbolAddress((void**)&p_hv, g_hv);
    cudaGetSymbolAddress((void**)&p_hg, g_hg);

    // 1. mixes + v_first copy
    mix_kernel<<<(int)((BTC + 255) / 256), 256>>>(x, vf, x_r, x_w, x_k, x_v, x_a, x_g, out_vf);

    dim3 gBig(Mrows / BM, Cdim / BN);   // (64, 16)

    // 2-4. big GEMMs (A @ W^T)
    gemm_abT<<<gBig, 256>>>(p_xr, Wr, out_r, Mrows, Cdim, Cdim);
    gemm_abT<<<gBig, 256>>>(p_xk, Wk, p_ko,  Mrows, Cdim, Cdim);
    gemm_abT<<<gBig, 256>>>(p_xv, Wv, p_vg,  Mrows, Cdim, Cdim);

    // 5-6. w path: hw = tanh(xw @ w1); w = -softplus(-(w0 + hw @ w2)) - 0.5
    gemm_ab<EPI_TANH><<<dim3(Mrows / BM, (DW + BN - 1) / BN), 256>>>(
        p_xw, w1, p_hw, Mrows, DW, Cdim, nullptr, nullptr, nullptr);
    gemm_ab<EPI_W><<<gBig, 256>>>(
        p_hw, w2, out_w, Mrows, Cdim, DW, w0, nullptr, nullptr);

    // 7-8. a path: ha = xa @ a1; a = sigmoid(a0 + ha @ a2)
    gemm_ab<EPI_NONE><<<dim3(Mrows / BM, (DA + BN - 1) / BN), 256>>>(
        p_xa, a1, p_ha, Mrows, DA, Cdim, nullptr, nullptr, nullptr);
    gemm_ab<EPI_SIG><<<gBig, 256>>>(
        p_ha, a2, out_a, Mrows, Cdim, DA, a0, nullptr, nullptr);

    // 9-10. v path: hv = xv @ v1; v = vg + (vf - vg) * sigmoid(v0 + hv @ v2)
    gemm_ab<EPI_NONE><<<dim3(Mrows / BM, (DV + BN - 1) / BN), 256>>>(
        p_xv, v1, p_hv, Mrows, DV, Cdim, nullptr, nullptr, nullptr);
    gemm_ab<EPI_VMIX><<<gBig, 256>>>(
        p_hv, v2, out_v, Mrows, Cdim, DV, v0, p_vg, vf);

    // 11-12. g path: hg = sigmoid(xg @ g1); g = hg @ g2
    gemm_ab<EPI_SIG><<<dim3(Mrows / BM, (DG + BN - 1) / BN), 256>>>(
        p_xg, g1, p_hg, Mrows, DG, Cdim, nullptr, nullptr, nullptr);
    gemm_ab<EPI_NONE><<<gBig, 256>>>(
        p_hg, g2, out_g, Mrows, Cdim, DG, nullptr, nullptr, nullptr);

    // 13. kk normalize + final k (needs a from step 8)
    int warps = Mrows * NHEAD;                 // 262144
    kk_fin_kernel<<<warps * 32 / 256, 256>>>(k_k, k_a, out_a, out_kk, out_k);
}

// round 4
// speedup vs baseline: 2.6926x; 2.6926x over previous
#include <cuda_runtime.h>
#include <cuda_bf16.h>
#include <math.h>
#include <stdint.h>

#define Bdim 2
#define Tdim 4096
#define Cdim 2048
#define HSZ  64
#define Mrows 8192
static const size_t BTC = (size_t)Mrows * Cdim;

// ---------------- scratch (fp32, tf32-rounded where noted) ----------------
__device__ float g_xr[(size_t)Mrows * Cdim];
__device__ float g_xw[(size_t)Mrows * Cdim];
__device__ float g_xk[(size_t)Mrows * Cdim];
__device__ float g_xv[(size_t)Mrows * Cdim];
__device__ float g_xa[(size_t)Mrows * Cdim];
__device__ float g_xg[(size_t)Mrows * Cdim];
__device__ float g_wr[(size_t)Cdim * Cdim];
__device__ float g_wk[(size_t)Cdim * Cdim];
__device__ float g_wv[(size_t)Cdim * Cdim];
__device__ float g_w1p[(size_t)128 * Cdim];
__device__ float g_a1p[(size_t)128 * Cdim];
__device__ float g_v1p[(size_t)128 * Cdim];
__device__ float g_g1p[(size_t)256 * Cdim];
__device__ float g_w2p[(size_t)Cdim * 128];
__device__ float g_a2p[(size_t)Cdim * 128];
__device__ float g_v2p[(size_t)Cdim * 128];
__device__ float g_g2p[(size_t)Cdim * 256];
__device__ float g_hw[(size_t)Mrows * 128];
__device__ float g_ha[(size_t)Mrows * 128];
__device__ float g_hv[(size_t)Mrows * 128];
__device__ float g_hg[(size_t)Mrows * 256];
__device__ float g_ko[(size_t)Mrows * Cdim];
__device__ float g_vg[(size_t)Mrows * Cdim];

// ---------------- helpers ----------------
__device__ __forceinline__ float tf32r(float x) {
    uint32_t u;
    asm("cvt.rna.tf32.f32 %0, %1;" : "=r"(u) : "f"(x));
    return __uint_as_float(u);
}
__device__ __forceinline__ float sigmoidf_(float y) { return 1.0f / (1.0f + expf(-y)); }

__device__ __forceinline__ void mma8(float* d, const uint32_t* a, const uint32_t* b) {
    asm volatile("mma.sync.aligned.m16n8k8.row.col.f32.tf32.tf32.f32 "
        "{%0,%1,%2,%3}, {%4,%5,%6,%7}, {%8,%9}, {%0,%1,%2,%3};"
        : "+f"(d[0]), "+f"(d[1]), "+f"(d[2]), "+f"(d[3])
        : "r"(a[0]), "r"(a[1]), "r"(a[2]), "r"(a[3]), "r"(b[0]), "r"(b[1]));
}

// ---------------- elementwise producers ----------------
__global__ __launch_bounds__(256) void mix_kernel(
    const float* __restrict__ x, const float* __restrict__ vf,
    const float* __restrict__ mr, const float* __restrict__ mw,
    const float* __restrict__ mk, const float* __restrict__ mv,
    const float* __restrict__ ma, const float* __restrict__ mg,
    float* __restrict__ out_vf)
{
    size_t idx = (size_t)blockIdx.x * blockDim.x + threadIdx.x;
    if (idx >= BTC) return;
    int c   = (int)(idx & (Cdim - 1));
    int row = (int)(idx >> 11);
    int t   = row & (Tdim - 1);
    float xc = x[idx];
    float xp = (t == 0) ? 0.0f : x[idx - Cdim];
    float xx = xp - xc;
    g_xr[idx] = tf32r(fmaf(xx, mr[c], xc));
    g_xw[idx] = tf32r(fmaf(xx, mw[c], xc));
    g_xk[idx] = tf32r(fmaf(xx, mk[c], xc));
    g_xv[idx] = tf32r(fmaf(xx, mv[c], xc));
    g_xa[idx] = tf32r(fmaf(xx, ma[c], xc));
    g_xg[idx] = tf32r(fmaf(xx, mg[c], xc));
    out_vf[idx] = vf[idx];
}

__global__ __launch_bounds__(256) void prep_w(const float* __restrict__ W, float* __restrict__ P, size_t n)
{
    size_t idx = (size_t)blockIdx.x * blockDim.x + threadIdx.x;
    if (idx < n) P[idx] = tf32r(W[idx]);
}
// w1 [C,D] -> p [Dp, C], zero-padded
__global__ __launch_bounds__(256) void prep_l1(const float* __restrict__ w1, float* __restrict__ p, int D_, int Dp)
{
    size_t idx = (size_t)blockIdx.x * blockDim.x + threadIdx.x;
    if (idx >= (size_t)Dp * Cdim) return;
    int nn = (int)(idx / Cdim), k = (int)(idx % Cdim);
    p[idx] = (nn < D_) ? tf32r(w1[(size_t)k * D_ + nn]) : 0.0f;
}
// w2 [D,C] -> p [C, Dp], zero-padded
__global__ __launch_bounds__(256) void prep_l2(const float* __restrict__ w2, float* __restrict__ p, int D_, int Dp)
{
    size_t idx = (size_t)blockIdx.x * blockDim.x + threadIdx.x;
    if (idx >= (size_t)Cdim * Dp) return;
    int nn = (int)(idx / Dp), d = (int)(idx % Dp);
    p[idx] = (d < D_) ? tf32r(w2[(size_t)d * Cdim + nn]) : 0.0f;
}

// ---------------- tf32 tensor-core GEMM ----------------
#define EPI_NONE 0
#define EPI_TANH 1
#define EPI_W    2
#define EPI_SIG  3
#define EPI_VMIX 4

#define KC 32
#define SSTR 137
#define BUFSZ (KC * SSTR)
#define SMBYTES (4 * BUFSZ * 4)

// O[M,N] = epi(A[M,K] @ Bm[N,K]^T); grid = (N/128, M/128), 256 threads
template <int EPI, int ROUND>
__global__ __launch_bounds__(256) void gemm_tf32(
    const float* __restrict__ A, const float* __restrict__ Bm,
    float* __restrict__ O, int K, int N,
    const float* __restrict__ bias,
    const float* __restrict__ vgp, const float* __restrict__ vfp)
{
    extern __shared__ float sm[];
    float* smA0 = sm;
    float* smA1 = sm + BUFSZ;
    float* smB0 = sm + 2 * BUFSZ;
    float* smB1 = sm + 3 * BUFSZ;

    const int tid  = threadIdx.x;
    const int lane = tid & 31;
    const int wid  = tid >> 5;
    const int wm   = (wid >> 2) * 64;
    const int wn   = (wid & 3) * 32;
    const int tq   = lane >> 2;
    const int tr   = lane & 3;
    const int n0   = blockIdx.x * 128;
    const int m0   = blockIdx.y * 128;

    const int lrow = tid >> 3;   // 0..31 (advance 32 per p)
    const int lj   = tid & 7;    // float4 chunk along K

    const float* Ap = A  + (size_t)m0 * K + lj * 4;
    const float* Bp = Bm + (size_t)n0 * K + lj * 4;

    float4 ra[4], rb[4];
    #pragma unroll
    for (int p = 0; p < 4; p++) {
        ra[p] = *(const float4*)&Ap[(size_t)(lrow + p * 32) * K];
        rb[p] = *(const float4*)&Bp[(size_t)(lrow + p * 32) * K];
    }

    float acc[4][4][4];
    #pragma unroll
    for (int i = 0; i < 4; i++)
        #pragma unroll
        for (int j = 0; j < 4; j++)
            #pragma unroll
            for (int q = 0; q < 4; q++) acc[i][j][q] = 0.0f;

    const int NIT = K >> 5;
    for (int it = 0; it < NIT; it++) {
        float* Ac = (it & 1) ? smA1 : smA0;
        float* Bc = (it & 1) ? smB1 : smB0;
        // store prefetched tile (transposed to k-major)
        #pragma unroll
        for (int p = 0; p < 4; p++) {
            int r = lrow + p * 32;
            const float* va = (const float*)&ra[p];
            const float* vb = (const float*)&rb[p];
            #pragma unroll
            for (int q = 0; q < 4; q++) {
                Ac[(lj * 4 + q) * SSTR + r] = va[q];
                Bc[(lj * 4 + q) * SSTR + r] = vb[q];
            }
        }
        __syncthreads();
        if (it + 1 < NIT) {
            size_t k0 = (size_t)(it + 1) << 5;
            #pragma unroll
            for (int p = 0; p < 4; p++) {
                ra[p] = *(const float4*)&Ap[(size_t)(lrow + p * 32) * K + k0];
                rb[p] = *(const float4*)&Bp[(size_t)(lrow + p * 32) * K + k0];
            }
        }
        // compute on current buffer
        #pragma unroll
        for (int ks = 0; ks < 4; ks++) {
            const float* a0p = Ac + (ks * 8 + tr) * SSTR + wm + tq;
            const float* b0p = Bc + (ks * 8 + tr) * SSTR + wn + tq;
            uint32_t af[4][4], bf[4][2];
            #pragma unroll
            for (int nf = 0; nf < 4; nf++) {
                bf[nf][0] = __float_as_uint(b0p[nf * 8]);
                bf[nf][1] = __float_as_uint(b0p[4 * SSTR + nf * 8]);
            }
            #pragma unroll
            for (int mf = 0; mf < 4; mf++) {
                af[mf][0] = __float_as_uint(a0p[mf * 16]);
                af[mf][1] = __float_as_uint(a0p[mf * 16 + 8]);
                af[mf][2] = __float_as_uint(a0p[4 * SSTR + mf * 16]);
                af[mf][3] = __float_as_uint(a0p[4 * SSTR + mf * 16 + 8]);
            }
            #pragma unroll
            for (int mf = 0; mf < 4; mf++)
                #pragma unroll
                for (int nf = 0; nf < 4; nf++)
                    mma8(acc[mf][nf], af[mf], bf[nf]);
        }
        __syncthreads();
    }

    // epilogue: write 16 frags, 2 float2 each
    #pragma unroll
    for (int mf = 0; mf < 4; mf++) {
        #pragma unroll
        for (int nf = 0; nf < 4; nf++) {
            int n = n0 + wn + nf * 8 + tr * 2;
            float bv0 = 0.0f, bv1 = 0.0f;
            if (EPI == EPI_W || EPI == EPI_SIG || EPI == EPI_VMIX) {
                if (bias) { bv0 = bias[n]; bv1 = bias[n + 1]; }
            }
            #pragma unroll
            for (int h = 0; h < 2; h++) {
                int m = m0 + wm + mf * 16 + tq + h * 8;
                float v0c = acc[mf][nf][h * 2 + 0];
                float v1c = acc[mf][nf][h * 2 + 1];
                float o0, o1;
                if (EPI == EPI_NONE)      { o0 = v0c; o1 = v1c; }
                else if (EPI == EPI_TANH) { o0 = tanhf(v0c); o1 = tanhf(v1c); }
                else if (EPI == EPI_SIG)  { o0 = sigmoidf_(v0c + bv0); o1 = sigmoidf_(v1c + bv1); }
                else if (EPI == EPI_W) {
                    float y0 = bv0 + v0c, y1 = bv1 + v1c;
                    o0 = -(fmaxf(-y0, 0.0f) + log1pf(expf(-fabsf(y0)))) - 0.5f;
                    o1 = -(fmaxf(-y1, 0.0f) + log1pf(expf(-fabsf(y1)))) - 0.5f;
                } else { // EPI_VMIX
                    float s0 = sigmoidf_(bv0 + v0c), s1 = sigmoidf_(bv1 + v1c);
                    size_t ix = (size_t)m * N + n;
                    float vg0 = vgp[ix], vg1 = vgp[ix + 1];
                    o0 = vg0 + (vfp[ix] - vg0) * s0;
                    o1 = vg1 + (vfp[ix + 1] - vg1) * s1;
                }
                if (ROUND) { o0 = tf32r(o0); o1 = tf32r(o1); }
                *(float2*)&O[(size_t)m * N + n] = make_float2(o0, o1);
            }
        }
    }
}

// ---------------- kk / final k ----------------
__global__ __launch_bounds__(256) void kk_fin_kernel(
    const float* __restrict__ k_k, const float* __restrict__ k_a,
    const float* __restrict__ a_out,
    float* __restrict__ out_kk, float* __restrict__ out_k)
{
    int gw   = (blockIdx.x * blockDim.x + threadIdx.x) >> 5;
    int lane = threadIdx.x & 31;
    int row  = gw >> 5;
    int h    = gw & 31;
    if (row >= Mrows) return;
    int bse = row * Cdim + h * HSZ;
    int c0 = h * HSZ + lane, c1 = c0 + 32;
    float k0v = g_ko[bse + lane];
    float k1v = g_ko[bse + 32 + lane];
    float kk0 = k0v * k_k[c0];
    float kk1 = k1v * k_k[c1];
    float ss = kk0 * kk0 + kk1 * kk1;
    #pragma unroll
    for (int o = 16; o > 0; o >>= 1) ss += __shfl_xor_sync(0xFFFFFFFFu, ss, o);
    float inv = 1.0f / fmaxf(sqrtf(ss), 1e-12f);
    out_kk[bse + lane]      = kk0 * inv;
    out_kk[bse + 32 + lane] = kk1 * inv;
    float a0v = a_out[bse + lane];
    float a1v = a_out[bse + 32 + lane];
    out_k[bse + lane]      = k0v * fmaf(a0v - 1.0f, k_a[c0], 1.0f);
    out_k[bse + 32 + lane] = k1v * fmaf(a1v - 1.0f, k_a[c1], 1.0f);
}

// ---------------- launch ----------------
template <typename T>
static T* sym(const void* s) { void* p; cudaGetSymbolAddress(&p, s); return (T*)p; }

extern "C" void kernel_launch(void* const* d_in, const int* in_sizes, int n_in,
                              void* d_out, int out_size)
{
    const float* x   = (const float*)d_in[0];
    const float* vf  = (const float*)d_in[1];
    const float* x_r = (const float*)d_in[2];
    const float* x_w = (const float*)d_in[3];
    const float* x_k = (const float*)d_in[4];
    const float* x_v = (const float*)d_in[5];
    const float* x_a = (const float*)d_in[6];
    const float* x_g = (const float*)d_in[7];
    const float* w0  = (const float*)d_in[8];
    const float* w1  = (const float*)d_in[9];
    const float* w2  = (const float*)d_in[10];
    const float* a0  = (const float*)d_in[11];
    const float* a1  = (const float*)d_in[12];
    const float* a2  = (const float*)d_in[13];
    const float* v0  = (const float*)d_in[14];
    const float* v1  = (const float*)d_in[15];
    const float* v2  = (const float*)d_in[16];
    const float* g1  = (const float*)d_in[17];
    const float* g2  = (const float*)d_in[18];
    const float* k_k = (const float*)d_in[19];
    const float* k_a = (const float*)d_in[20];
    const float* Wr  = (const float*)d_in[21];
    const float* Wk  = (const float*)d_in[22];
    const float* Wv  = (const float*)d_in[23];
    (void)in_sizes; (void)n_in; (void)out_size;

    float* out = (float*)d_out;
    float* out_r  = out + 0 * BTC;
    float* out_w  = out + 1 * BTC;
    float* out_k  = out + 2 * BTC;
    float* out_v  = out + 3 * BTC;
    float* out_a  = out + 4 * BTC;
    float* out_g  = out + 5 * BTC;
    float* out_kk = out + 6 * BTC;
    float* out_vf = out + 7 * BTC;

    float* p_xr = sym<float>(&g_xr);  float* p_xw = sym<float>(&g_xw);
    float* p_xk = sym<float>(&g_xk);  float* p_xv = sym<float>(&g_xv);
    float* p_xa = sym<float>(&g_xa);  float* p_xg = sym<float>(&g_xg);
    float* p_wr = sym<float>(&g_wr);  float* p_wk = sym<float>(&g_wk);
    float* p_wv = sym<float>(&g_wv);
    float* p_w1 = sym<float>(&g_w1p); float* p_a1 = sym<float>(&g_a1p);
    float* p_v1 = sym<float>(&g_v1p); float* p_g1 = sym<float>(&g_g1p);
    float* p_w2 = sym<float>(&g_w2p); float* p_a2 = sym<float>(&g_a2p);
    float* p_v2 = sym<float>(&g_v2p); float* p_g2 = sym<float>(&g_g2p);
    float* p_hw = sym<float>(&g_hw);  float* p_ha = sym<float>(&g_ha);
    float* p_hv = sym<float>(&g_hv);  float* p_hg = sym<float>(&g_hg);
    float* p_ko = sym<float>(&g_ko);  float* p_vg = sym<float>(&g_vg);

    cudaFuncSetAttribute(gemm_tf32<EPI_NONE,0>, cudaFuncAttributeMaxDynamicSharedMemorySize, SMBYTES);
    cudaFuncSetAttribute(gemm_tf32<EPI_NONE,1>, cudaFuncAttributeMaxDynamicSharedMemorySize, SMBYTES);
    cudaFuncSetAttribute(gemm_tf32<EPI_TANH,1>, cudaFuncAttributeMaxDynamicSharedMemorySize, SMBYTES);
    cudaFuncSetAttribute(gemm_tf32<EPI_SIG,1>,  cudaFuncAttributeMaxDynamicSharedMemorySize, SMBYTES);
    cudaFuncSetAttribute(gemm_tf32<EPI_SIG,0>,  cudaFuncAttributeMaxDynamicSharedMemorySize, SMBYTES);
    cudaFuncSetAttribute(gemm_tf32<EPI_W,0>,    cudaFuncAttributeMaxDynamicSharedMemorySize, SMBYTES);
    cudaFuncSetAttribute(gemm_tf32<EPI_VMIX,0>, cudaFuncAttributeMaxDynamicSharedMemorySize, SMBYTES);

    // 1. mix (tf32-rounded activations) + vf copy
    mix_kernel<<<(int)((BTC + 255) / 256), 256>>>(x, vf, x_r, x_w, x_k, x_v, x_a, x_g, out_vf);

    // 2. weight preps (tf32-rounded)
    size_t nCC = (size_t)Cdim * Cdim;
    prep_w<<<(int)((nCC + 255) / 256), 256>>>(Wr, p_wr, nCC);
    prep_w<<<(int)((nCC + 255) / 256), 256>>>(Wk, p_wk, nCC);
    prep_w<<<(int)((nCC + 255) / 256), 256>>>(Wv, p_wv, nCC);
    prep_l1<<<(128 * Cdim + 255) / 256, 256>>>(w1, p_w1, 128, 128);
    prep_l1<<<(128 * Cdim + 255) / 256, 256>>>(a1, p_a1, 128, 128);
    prep_l1<<<(128 * Cdim + 255) / 256, 256>>>(v1, p_v1, 64, 128);
    prep_l1<<<(256 * Cdim + 255) / 256, 256>>>(g1, p_g1, 224, 256);
    prep_l2<<<(Cdim * 128 + 255) / 256, 256>>>(w2, p_w2, 128, 128);
    prep_l2<<<(Cdim * 128 + 255) / 256, 256>>>(a2, p_a2, 128, 128);
    prep_l2<<<(Cdim * 128 + 255) / 256, 256>>>(v2, p_v2, 64, 128);
    prep_l2<<<(Cdim * 256 + 255) / 256, 256>>>(g2, p_g2, 224, 256);

    dim3 gBig(Cdim / 128, Mrows / 128);   // (16, 64)
    dim3 gS1(1, Mrows / 128);
    dim3 gS1g(2, Mrows / 128);

    // 3. big GEMMs
    gemm_tf32<EPI_NONE,0><<<gBig, 256, SMBYTES>>>(p_xr, p_wr, out_r, Cdim, Cdim, nullptr, nullptr, nullptr);
    gemm_tf32<EPI_NONE,0><<<gBig, 256, SMBYTES>>>(p_xk, p_wk, p_ko,  Cdim, Cdim, nullptr, nullptr, nullptr);
    gemm_tf32<EPI_NONE,0><<<gBig, 256, SMBYTES>>>(p_xv, p_wv, p_vg,  Cdim, Cdim, nullptr, nullptr, nullptr);

    // 4. LoRA stage 1 (outputs tf32-rounded for stage 2)
    gemm_tf32<EPI_TANH,1><<<gS1,  256, SMBYTES>>>(p_xw, p_w1, p_hw, Cdim, 128, nullptr, nullptr, nullptr);
    gemm_tf32<EPI_NONE,1><<<gS1,  256, SMBYTES>>>(p_xa, p_a1, p_ha, Cdim, 128, nullptr, nullptr, nullptr);
    gemm_tf32<EPI_NONE,1><<<gS1,  256, SMBYTES>>>(p_xv, p_v1, p_hv, Cdim, 128, nullptr, nullptr, nullptr);
    gemm_tf32<EPI_SIG,1><<<gS1g, 256, SMBYTES>>>(p_xg, p_g1, p_hg, Cdim, 256, nullptr, nullptr, nullptr);

    // 5. LoRA stage 2 (fused epilogues)
    gemm_tf32<EPI_W,0><<<gBig, 256, SMBYTES>>>(p_hw, p_w2, out_w, 128, Cdim, w0, nullptr, nullptr);
    gemm_tf32<EPI_SIG,0><<<gBig, 256, SMBYTES>>>(p_ha, p_a2, out_a, 128, Cdim, a0, nullptr, nullptr);
    gemm_tf32<EPI_VMIX,0><<<gBig, 256, SMBYTES>>>(p_hv, p_v2, out_v, 128, Cdim, v0, p_vg, vf);
    gemm_tf32<EPI_NONE,0><<<gBig, 256, SMBYTES>>>(p_hg, p_g2, out_g, 256, Cdim, nullptr, nullptr, nullptr);

    // 6. kk normalize + final k
    kk_fin_kernel<<<Mrows * 32 * 32 / 256, 256>>>(k_k, k_a, out_a, out_kk, out_k);
}

// round 5
// speedup vs baseline: 4.5727x; 1.6983x over previous
#include <cuda_runtime.h>
#include <cuda_fp16.h>
#include <math.h>
#include <stdint.h>

#define Bdim 2
#define Tdim 4096
#define Cdim 2048
#define HSZ  64
#define Mrows 8192
static const size_t BTC = (size_t)Mrows * Cdim;

// ---------------- scratch ----------------
__device__ __half g_xr[(size_t)Mrows * Cdim];
__device__ __half g_xw[(size_t)Mrows * Cdim];
__device__ __half g_xk[(size_t)Mrows * Cdim];
__device__ __half g_xv[(size_t)Mrows * Cdim];
__device__ __half g_xa[(size_t)Mrows * Cdim];
__device__ __half g_xg[(size_t)Mrows * Cdim];
__device__ __half g_wr[(size_t)Cdim * Cdim];
__device__ __half g_wk[(size_t)Cdim * Cdim];
__device__ __half g_wv[(size_t)Cdim * Cdim];
__device__ __half g_w1p[(size_t)128 * Cdim];
__device__ __half g_a1p[(size_t)128 * Cdim];
__device__ __half g_v1p[(size_t)128 * Cdim];
__device__ __half g_g1p[(size_t)256 * Cdim];
__device__ __half g_w2p[(size_t)Cdim * 128];
__device__ __half g_a2p[(size_t)Cdim * 128];
__device__ __half g_v2p[(size_t)Cdim * 128];
__device__ __half g_g2p[(size_t)Cdim * 256];
__device__ __half g_hw[(size_t)Mrows * 128];
__device__ __half g_ha[(size_t)Mrows * 128];
__device__ __half g_hv[(size_t)Mrows * 128];
__device__ __half g_hg[(size_t)Mrows * 256];
__device__ float  g_ko[(size_t)Mrows * Cdim];
__device__ float  g_vg[(size_t)Mrows * Cdim];

// ---------------- helpers ----------------
__device__ __forceinline__ float sigmoidf_(float y) { return 1.0f / (1.0f + expf(-y)); }

__device__ __forceinline__ void mma16(float* d, const uint32_t* a, const uint32_t* b) {
    asm volatile("mma.sync.aligned.m16n8k16.row.col.f32.f16.f16.f32 "
        "{%0,%1,%2,%3}, {%4,%5,%6,%7}, {%8,%9}, {%0,%1,%2,%3};"
        : "+f"(d[0]), "+f"(d[1]), "+f"(d[2]), "+f"(d[3])
        : "r"(a[0]), "r"(a[1]), "r"(a[2]), "r"(a[3]), "r"(b[0]), "r"(b[1]));
}

#define ASTR 40               // halves per smem row (32 + 8 pad)
#define BUFH (128 * ASTR)     // halves per buffer

// ---------------- GEMM mainloop (fp16, 128x128 tile, KC=32) ----------------
// acc over A[M,K]h @ Bm[N,K]h^T tile at (m0, n0). 256 threads, 8 warps 2x4 of 64x32.
__device__ __forceinline__ void mainloop_h(
    const __half* __restrict__ A, const __half* __restrict__ Bm,
    int K, int m0, int n0, __half* smA, __half* smB, float acc[4][4][4])
{
    const int tid  = threadIdx.x;
    const int lane = tid & 31;
    const int wid  = tid >> 5;
    const int wm   = (wid >> 2) * 64;
    const int wn   = (wid & 3) * 32;
    const int tq   = lane >> 2;
    const int tr   = lane & 3;
    const int ml   = tid >> 1;
    const int cl   = (tid & 1) * 16;

    const __half* Ap = A  + (size_t)(m0 + ml) * K + cl;
    const __half* Bp = Bm + (size_t)(n0 + ml) * K + cl;

    uint4 ra0 = *(const uint4*)Ap;
    uint4 ra1 = *(const uint4*)(Ap + 8);
    uint4 rb0 = *(const uint4*)Bp;
    uint4 rb1 = *(const uint4*)(Bp + 8);

    const int NIT = K >> 5;
    for (int it = 0; it < NIT; it++) {
        __half* Ac = smA + (it & 1) * BUFH;
        __half* Bc = smB + (it & 1) * BUFH;
        *(uint4*)(Ac + ml * ASTR + cl)     = ra0;
        *(uint4*)(Ac + ml * ASTR + cl + 8) = ra1;
        *(uint4*)(Bc + ml * ASTR + cl)     = rb0;
        *(uint4*)(Bc + ml * ASTR + cl + 8) = rb1;
        __syncthreads();
        if (it + 1 < NIT) {
            size_t k0 = (size_t)(it + 1) << 5;
            ra0 = *(const uint4*)(Ap + k0);
            ra1 = *(const uint4*)(Ap + k0 + 8);
            rb0 = *(const uint4*)(Bp + k0);
            rb1 = *(const uint4*)(Bp + k0 + 8);
        }
        #pragma unroll
        for (int kb = 0; kb < 2; kb++) {
            const int ko = kb * 16 + 2 * tr;
            uint32_t af[4][4], bf[4][2];
            #pragma unroll
            for (int nf = 0; nf < 4; nf++) {
                const __half* bp = Bc + (wn + nf * 8 + tq) * ASTR + ko;
                bf[nf][0] = *(const uint32_t*)bp;
                bf[nf][1] = *(const uint32_t*)(bp + 8);
            }
            #pragma unroll
            for (int mf = 0; mf < 4; mf++) {
                const __half* ap = Ac + (wm + mf * 16 + tq) * ASTR + ko;
                af[mf][0] = *(const uint32_t*)ap;
                af[mf][1] = *(const uint32_t*)(ap + 8 * ASTR);
                af[mf][2] = *(const uint32_t*)(ap + 8);
                af[mf][3] = *(const uint32_t*)(ap + 8 * ASTR + 8);
            }
            #pragma unroll
            for (int mf = 0; mf < 4; mf++)
                #pragma unroll
                for (int nf = 0; nf < 4; nf++)
                    mma16(acc[mf][nf], af[mf], bf[nf]);
        }
        __syncthreads();
    }
}

// ---------------- main GEMM kernels ----------------
#define EPI_NONE 0
#define EPI_TANH 1
#define EPI_W    2
#define EPI_SIG  3
#define EPI_VMIX 4

template <int EPI>
__global__ __launch_bounds__(256) void gemm_h(
    const __half* __restrict__ A, const __half* __restrict__ Bm,
    float* __restrict__ O, int K, int N,
    const float* __restrict__ bias,
    const float* __restrict__ vgp, const float* __restrict__ vfp)
{
    __shared__ __half smA[2 * BUFH];
    __shared__ __half smB[2 * BUFH];
    const int n0 = blockIdx.x * 128;
    const int m0 = blockIdx.y * 128;
    float acc[4][4][4];
    #pragma unroll
    for (int i = 0; i < 4; i++)
        #pragma unroll
        for (int j = 0; j < 4; j++)
            #pragma unroll
            for (int q = 0; q < 4; q++) acc[i][j][q] = 0.0f;

    mainloop_h(A, Bm, K, m0, n0, smA, smB, acc);

    const int lane = threadIdx.x & 31;
    const int wid  = threadIdx.x >> 5;
    const int wm = (wid >> 2) * 64, wn = (wid & 3) * 32;
    const int tq = lane >> 2, tr = lane & 3;

    #pragma unroll
    for (int mf = 0; mf < 4; mf++) {
        #pragma unroll
        for (int nf = 0; nf < 4; nf++) {
            int n = n0 + wn + nf * 8 + tr * 2;
            float bv0 = 0.0f, bv1 = 0.0f;
            if (EPI == EPI_W || EPI == EPI_SIG || EPI == EPI_VMIX) {
                bv0 = bias[n]; bv1 = bias[n + 1];
            }
            #pragma unroll
            for (int h = 0; h < 2; h++) {
                int m = m0 + wm + mf * 16 + tq + h * 8;
                float v0c = acc[mf][nf][h * 2 + 0];
                float v1c = acc[mf][nf][h * 2 + 1];
                float o0, o1;
                if (EPI == EPI_NONE)      { o0 = v0c; o1 = v1c; }
                else if (EPI == EPI_SIG)  { o0 = sigmoidf_(v0c + bv0); o1 = sigmoidf_(v1c + bv1); }
                else if (EPI == EPI_W) {
                    float y0 = bv0 + v0c, y1 = bv1 + v1c;
                    o0 = -(fmaxf(-y0, 0.0f) + log1pf(expf(-fabsf(y0)))) - 0.5f;
                    o1 = -(fmaxf(-y1, 0.0f) + log1pf(expf(-fabsf(y1)))) - 0.5f;
                } else { // EPI_VMIX
                    float s0 = sigmoidf_(bv0 + v0c), s1 = sigmoidf_(bv1 + v1c);
                    size_t ix = (size_t)m * N + n;
                    float vg0 = vgp[ix], vg1 = vgp[ix + 1];
                    o0 = vg0 + (vfp[ix] - vg0) * s0;
                    o1 = vg1 + (vfp[ix + 1] - vg1) * s1;
                }
                *(float2*)&O[(size_t)m * N + n] = make_float2(o0, o1);
            }
        }
    }
}

// LoRA stage-1: z-batched (xw->hw tanh, xa->ha, xv->hv, xg->hg sig), half output
__global__ __launch_bounds__(256) void gemm_s1(void)
{
    const int z = blockIdx.z;
    const __half* A;
    const __half* Bm;
    __half* Oh;
    int N, epi;
    if (z == 0)      { A = g_xw; Bm = g_w1p; Oh = g_hw; N = 128; epi = EPI_TANH; }
    else if (z == 1) { A = g_xa; Bm = g_a1p; Oh = g_ha; N = 128; epi = EPI_NONE; }
    else if (z == 2) { A = g_xv; Bm = g_v1p; Oh = g_hv; N = 128; epi = EPI_NONE; }
    else             { A = g_xg; Bm = g_g1p; Oh = g_hg; N = 256; epi = EPI_SIG; }

    const int n0 = blockIdx.x * 128;
    const int m0 = blockIdx.y * 128;
    if (n0 >= N) return;

    __shared__ __half smA[2 * BUFH];
    __shared__ __half smB[2 * BUFH];
    float acc[4][4][4];
    #pragma unroll
    for (int i = 0; i < 4; i++)
        #pragma unroll
        for (int j = 0; j < 4; j++)
            #pragma unroll
            for (int q = 0; q < 4; q++) acc[i][j][q] = 0.0f;

    mainloop_h(A, Bm, Cdim, m0, n0, smA, smB, acc);

    const int lane = threadIdx.x & 31;
    const int wid  = threadIdx.x >> 5;
    const int wm = (wid >> 2) * 64, wn = (wid & 3) * 32;
    const int tq = lane >> 2, tr = lane & 3;

    #pragma unroll
    for (int mf = 0; mf < 4; mf++) {
        #pragma unroll
        for (int nf = 0; nf < 4; nf++) {
            int n = n0 + wn + nf * 8 + tr * 2;
            #pragma unroll
            for (int h = 0; h < 2; h++) {
                int m = m0 + wm + mf * 16 + tq + h * 8;
                float v0c = acc[mf][nf][h * 2 + 0];
                float v1c = acc[mf][nf][h * 2 + 1];
                float o0, o1;
                if (epi == EPI_TANH)     { o0 = tanhf(v0c); o1 = tanhf(v1c); }
                else if (epi == EPI_SIG) { o0 = sigmoidf_(v0c); o1 = sigmoidf_(v1c); }
                else                     { o0 = v0c; o1 = v1c; }
                *(__half2*)&Oh[(size_t)m * N + n] = __floats2half2_rn(o0, o1);
            }
        }
    }
}

// ---------------- elementwise producers ----------------
__global__ __launch_bounds__(256) void mix_kernel(
    const float* __restrict__ x, const float* __restrict__ vf,
    const float* __restrict__ mr, const float* __restrict__ mw,
    const float* __restrict__ mk, const float* __restrict__ mv,
    const float* __restrict__ ma, const float* __restrict__ mg,
    float* __restrict__ out_vf)
{
    size_t idx = (size_t)blockIdx.x * blockDim.x + threadIdx.x;
    if (idx >= BTC) return;
    int c   = (int)(idx & (Cdim - 1));
    int row = (int)(idx >> 11);
    int t   = row & (Tdim - 1);
    float xc = x[idx];
    float xp = (t == 0) ? 0.0f : x[idx - Cdim];
    float xx = xp - xc;
    g_xr[idx] = __float2half(fmaf(xx, mr[c], xc));
    g_xw[idx] = __float2half(fmaf(xx, mw[c], xc));
    g_xk[idx] = __float2half(fmaf(xx, mk[c], xc));
    g_xv[idx] = __float2half(fmaf(xx, mv[c], xc));
    g_xa[idx] = __float2half(fmaf(xx, ma[c], xc));
    g_xg[idx] = __float2half(fmaf(xx, mg[c], xc));
    out_vf[idx] = vf[idx];
}

__global__ __launch_bounds__(256) void prep_big(
    const float* __restrict__ Wr, const float* __restrict__ Wk, const float* __restrict__ Wv)
{
    size_t idx = (size_t)blockIdx.x * blockDim.x + threadIdx.x;
    if (idx >= (size_t)Cdim * Cdim) return;
    int z = blockIdx.z;
    const float* W = (z == 0) ? Wr : (z == 1) ? Wk : Wv;
    __half* P = (z == 0) ? g_wr : (z == 1) ? g_wk : g_wv;
    P[idx] = __float2half(W[idx]);
}

// w1 [C,D] -> p [Dp, C] half, zero-padded
__global__ __launch_bounds__(256) void prep_l1(const float* __restrict__ w1, __half* __restrict__ p, int D_, int Dp)
{
    size_t idx = (size_t)blockIdx.x * blockDim.x + threadIdx.x;
    if (idx >= (size_t)Dp * Cdim) return;
    int nn = (int)(idx / Cdim), k = (int)(idx % Cdim);
    p[idx] = __float2half((nn < D_) ? w1[(size_t)k * D_ + nn] : 0.0f);
}
// w2 [D,C] -> p [C, Dp] half, zero-padded
__global__ __launch_bounds__(256) void prep_l2(const float* __restrict__ w2, __half* __restrict__ p, int D_, int Dp)
{
    size_t idx = (size_t)blockIdx.x * blockDim.x + threadIdx.x;
    if (idx >= (size_t)Cdim * Dp) return;
    int nn = (int)(idx / Dp), d = (int)(idx % Dp);
    p[idx] = __float2half((d < D_) ? w2[(size_t)d * Cdim + nn] : 0.0f);
}

// ---------------- kk / final k ----------------
__global__ __launch_bounds__(256) void kk_fin_kernel(
    const float* __restrict__ k_k, const float* __restrict__ k_a,
    const float* __restrict__ a_out,
    float* __restrict__ out_kk, float* __restrict__ out_k)
{
    int gw   = (blockIdx.x * blockDim.x + threadIdx.x) >> 5;
    int lane = threadIdx.x & 31;
    int row  = gw >> 5;
    int h    = gw & 31;
    if (row >= Mrows) return;
    int bse = row * Cdim + h * HSZ;
    int c0 = h * HSZ + lane, c1 = c0 + 32;
    float k0v = g_ko[bse + lane];
    float k1v = g_ko[bse + 32 + lane];
    float kk0 = k0v * k_k[c0];
    float kk1 = k1v * k_k[c1];
    float ss = kk0 * kk0 + kk1 * kk1;
    #pragma unroll
    for (int o = 16; o > 0; o >>= 1) ss += __shfl_xor_sync(0xFFFFFFFFu, ss, o);
    float inv = 1.0f / fmaxf(sqrtf(ss), 1e-12f);
    out_kk[bse + lane]      = kk0 * inv;
    out_kk[bse + 32 + lane] = kk1 * inv;
    float a0v = a_out[bse + lane];
    float a1v = a_out[bse + 32 + lane];
    out_k[bse + lane]      = k0v * fmaf(a0v - 1.0f, k_a[c0], 1.0f);
    out_k[bse + 32 + lane] = k1v * fmaf(a1v - 1.0f, k_a[c1], 1.0f);
}

// ---------------- launch ----------------
template <typename T>
static T* sym(const void* s) { void* p; cudaGetSymbolAddress(&p, s); return (T*)p; }

extern "C" void kernel_launch(void* const* d_in, const int* in_sizes, int n_in,
                              void* d_out, int out_size)
{
    const float* x   = (const float*)d_in[0];
    const float* vf  = (const float*)d_in[1];
    const float* x_r = (const float*)d_in[2];
    const float* x_w = (const float*)d_in[3];
    const float* x_k = (const float*)d_in[4];
    const float* x_v = (const float*)d_in[5];
    const float* x_a = (const float*)d_in[6];
    const float* x_g = (const float*)d_in[7];
    const float* w0  = (const float*)d_in[8];
    const float* w1  = (const float*)d_in[9];
    const float* w2  = (const float*)d_in[10];
    const float* a0  = (const float*)d_in[11];
    const float* a1  = (const float*)d_in[12];
    const float* a2  = (const float*)d_in[13];
    const float* v0  = (const float*)d_in[14];
    const float* v1  = (const float*)d_in[15];
    const float* v2  = (const float*)d_in[16];
    const float* g1  = (const float*)d_in[17];
    const float* g2  = (const float*)d_in[18];
    const float* k_k = (const float*)d_in[19];
    const float* k_a = (const float*)d_in[20];
    const float* Wr  = (const float*)d_in[21];
    const float* Wk  = (const float*)d_in[22];
    const float* Wv  = (const float*)d_in[23];
    (void)in_sizes; (void)n_in; (void)out_size;

    float* out = (float*)d_out;
    float* out_r  = out + 0 * BTC;
    float* out_w  = out + 1 * BTC;
    float* out_k  = out + 2 * BTC;
    float* out_v  = out + 3 * BTC;
    float* out_a  = out + 4 * BTC;
    float* out_g  = out + 5 * BTC;
    float* out_kk = out + 6 * BTC;
    float* out_vf = out + 7 * BTC;

    __half* p_xr = sym<__half>(&g_xr);  __half* p_xk = sym<__half>(&g_xk);
    __half* p_xv = sym<__half>(&g_xv);
    __half* p_wr = sym<__half>(&g_wr);  __half* p_wk = sym<__half>(&g_wk);
    __half* p_wv = sym<__half>(&g_wv);
    __half* p_w1 = sym<__half>(&g_w1p); __half* p_a1 = sym<__half>(&g_a1p);
    __half* p_v1 = sym<__half>(&g_v1p); __half* p_g1 = sym<__half>(&g_g1p);
    __half* p_w2 = sym<__half>(&g_w2p); __half* p_a2 = sym<__half>(&g_a2p);
    __half* p_v2 = sym<__half>(&g_v2p); __half* p_g2 = sym<__half>(&g_g2p);
    __half* p_hw = sym<__half>(&g_hw);  __half* p_ha = sym<__half>(&g_ha);
    __half* p_hv = sym<__half>(&g_hv);  __half* p_hg = sym<__half>(&g_hg);
    float*  p_ko = sym<float>(&g_ko);   float*  p_vg = sym<float>(&g_vg);

    // 1. mix (fp16 activations) + vf copy
    mix_kernel<<<(int)((BTC + 255) / 256), 256>>>(x, vf, x_r, x_w, x_k, x_v, x_a, x_g, out_vf);

    // 2. weight preps
    prep_big<<<dim3((unsigned)(((size_t)Cdim * Cdim + 255) / 256), 1, 3), 256>>>(Wr, Wk, Wv);
    prep_l1<<<(128 * Cdim + 255) / 256, 256>>>(w1, p_w1, 128, 128);
    prep_l1<<<(128 * Cdim + 255) / 256, 256>>>(a1, p_a1, 128, 128);
    prep_l1<<<(128 * Cdim + 255) / 256, 256>>>(v1, p_v1, 64, 128);
    prep_l1<<<(256 * Cdim + 255) / 256, 256>>>(g1, p_g1, 224, 256);
    prep_l2<<<(Cdim * 128 + 255) / 256, 256>>>(w2, p_w2, 128, 128);
    prep_l2<<<(Cdim * 128 + 255) / 256, 256>>>(a2, p_a2, 128, 128);
    prep_l2<<<(Cdim * 128 + 255) / 256, 256>>>(v2, p_v2, 64, 128);
    prep_l2<<<(Cdim * 256 + 255) / 256, 256>>>(g2, p_g2, 224, 256);

    dim3 gBig(Cdim / 128, Mrows / 128);   // (16, 64)

    // 3. big GEMMs
    gemm_h<EPI_NONE><<<gBig, 256>>>(p_xr, p_wr, out_r, Cdim, Cdim, nullptr, nullptr, nullptr);
    gemm_h<EPI_NONE><<<gBig, 256>>>(p_xk, p_wk, p_ko,  Cdim, Cdim, nullptr, nullptr, nullptr);
    gemm_h<EPI_NONE><<<gBig, 256>>>(p_xv, p_wv, p_vg,  Cdim, Cdim, nullptr, nullptr, nullptr);

    // 4. LoRA stage 1 (merged, half outputs)
    gemm_s1<<<dim3(2, Mrows / 128, 4), 256>>>();

    // 5. LoRA stage 2 (fused epilogues)
    gemm_h<EPI_W><<<gBig, 256>>>(p_hw, p_w2, out_w, 128, Cdim, w0, nullptr, nullptr);
    gemm_h<EPI_SIG><<<gBig, 256>>>(p_ha, p_a2, out_a, 128, Cdim, a0, nullptr, nullptr);
    gemm_h<EPI_VMIX><<<gBig, 256>>>(p_hv, p_v2, out_v, 128, Cdim, v0, p_vg, vf);
    gemm_h<EPI_NONE><<<gBig, 256>>>(p_hg, p_g2, out_g, 256, Cdim, nullptr, nullptr, nullptr);

    // 6. kk normalize + final k
    kk_fin_kernel<<<Mrows * 32 * 32 / 256, 256>>>(k_k, k_a, out_a, out_kk, out_k);
}

// round 6
// speedup vs baseline: 7.0830x; 1.5490x over previous
#include <cuda_runtime.h>
#include <cuda_fp16.h>
#include <math.h>
#include <stdint.h>

#define Bdim 2
#define Tdim 4096
#define Cdim 2048
#define HSZ  64
#define Mrows 8192
static const size_t BTC = (size_t)Mrows * Cdim;

// ---------------- scratch ----------------
__device__ __half g_xr[(size_t)Mrows * Cdim];
__device__ __half g_xw[(size_t)Mrows * Cdim];
__device__ __half g_xk[(size_t)Mrows * Cdim];
__device__ __half g_xv[(size_t)Mrows * Cdim];
__device__ __half g_xa[(size_t)Mrows * Cdim];
__device__ __half g_xg[(size_t)Mrows * Cdim];
__device__ __half g_wr[(size_t)Cdim * Cdim];
__device__ __half g_wk[(size_t)Cdim * Cdim];
__device__ __half g_wv[(size_t)Cdim * Cdim];
__device__ __half g_w1p[(size_t)128 * Cdim];
__device__ __half g_a1p[(size_t)128 * Cdim];
__device__ __half g_v1p[(size_t)128 * Cdim];
__device__ __half g_g1p[(size_t)256 * Cdim];
__device__ __half g_w2p[(size_t)Cdim * 128];
__device__ __half g_a2p[(size_t)Cdim * 128];
__device__ __half g_v2p[(size_t)Cdim * 128];
__device__ __half g_g2p[(size_t)Cdim * 256];
__device__ __half g_hw[(size_t)Mrows * 128];
__device__ __half g_ha[(size_t)Mrows * 128];
__device__ __half g_hv[(size_t)Mrows * 128];
__device__ __half g_hg[(size_t)Mrows * 256];
__device__ float  g_ko[(size_t)Mrows * Cdim];
__device__ float  g_vg[(size_t)Mrows * Cdim];

// ---------------- helpers ----------------
__device__ __forceinline__ float sigmoidf_(float y) { return 1.0f / (1.0f + expf(-y)); }

__device__ __forceinline__ uint32_t smem_u32(const void* p) {
    uint32_t a;
    asm("{ .reg .u64 t; cvta.to.shared.u64 t, %1; cvt.u32.u64 %0, t; }" : "=r"(a) : "l"(p));
    return a;
}
__device__ __forceinline__ void mma16(float* d, const uint32_t* a, const uint32_t* b) {
    asm volatile("mma.sync.aligned.m16n8k16.row.col.f32.f16.f16.f32 "
        "{%0,%1,%2,%3}, {%4,%5,%6,%7}, {%8,%9}, {%0,%1,%2,%3};"
        : "+f"(d[0]), "+f"(d[1]), "+f"(d[2]), "+f"(d[3])
        : "r"(a[0]), "r"(a[1]), "r"(a[2]), "r"(a[3]), "r"(b[0]), "r"(b[1]));
}
__device__ __forceinline__ void cpa16(uint32_t dst, const __half* src) {
    asm volatile("cp.async.cg.shared.global [%0], [%1], 16;"
        :: "r"(dst), "l"(__cvta_generic_to_global(src)));
}
#define CP_COMMIT() asm volatile("cp.async.commit_group;" ::: "memory")
#define CP_WAIT1()  asm volatile("cp.async.wait_group 1;" ::: "memory")
#define LDSM4(r0,r1,r2,r3,addr) \
    asm volatile("ldmatrix.sync.aligned.m8n8.x4.shared.b16 {%0,%1,%2,%3}, [%4];" \
        : "=r"(r0), "=r"(r1), "=r"(r2), "=r"(r3) : "r"(addr))

// stage size: 128 rows x 32 halves = 8192 bytes per operand
#define STGB 8192

// ---------------- mainloop: 128x128 tile, KC=32, 3-stage cp.async, ldmatrix ----
__device__ __forceinline__ void mainloop(
    const __half* __restrict__ A, const __half* __restrict__ Bm,
    int K, int m0, int n0, uint32_t sA, uint32_t sB, float acc[4][4][4])
{
    const int tid  = threadIdx.x;
    const int lane = tid & 31;
    const int wid  = tid >> 5;
    const int wm   = (wid >> 2) * 64;
    const int wn   = (wid & 3) * 32;

    // cp.async mapping: thread -> rows rA, rA+64, chunk cA (16B)
    const int rA  = tid >> 2;
    const int cA  = tid & 3;
    const int rA2 = rA + 64;
    const uint32_t o0 = rA  * 64 + ((cA ^ ((rA  >> 1) & 3)) * 16);
    const uint32_t o1 = rA2 * 64 + ((cA ^ ((rA2 >> 1) & 3)) * 16);
    const __half* Ag0 = A  + (size_t)(m0 + rA)  * K + cA * 8;
    const __half* Ag1 = A  + (size_t)(m0 + rA2) * K + cA * 8;
    const __half* Bg0 = Bm + (size_t)(n0 + rA)  * K + cA * 8;
    const __half* Bg1 = Bm + (size_t)(n0 + rA2) * K + cA * 8;

    // ldmatrix lane geometry
    const int rowadd = (lane & 7) + ((lane >> 3) & 1) * 8;  // row within 16-row block
    const int swz    = (rowadd >> 1) & 3;
    const int cbit   = lane >> 4;                           // k-chunk select 0/1

    const int NIT = K >> 5;
    #pragma unroll
    for (int s = 0; s < 2; s++) {
        const int k0 = s << 5;
        cpa16(sA + s * STGB + o0, Ag0 + k0);
        cpa16(sA + s * STGB + o1, Ag1 + k0);
        cpa16(sB + s * STGB + o0, Bg0 + k0);
        cpa16(sB + s * STGB + o1, Bg1 + k0);
        CP_COMMIT();
    }
    CP_WAIT1();
    __syncthreads();

    int s = 0;
    for (int it = 0; it < NIT; it++) {
        const uint32_t bA = sA + s * STGB;
        const uint32_t bB = sB + s * STGB;
        #pragma unroll
        for (int kb = 0; kb < 2; kb++) {
            const uint32_t choff = (uint32_t)((((kb << 1) + cbit) ^ swz) * 16);
            const uint32_t aaddr = bA + (wm + rowadd) * 64 + choff;
            const uint32_t baddr = bB + (wn + rowadd) * 64 + choff;
            uint32_t af[4][4], br[2][4];
            #pragma unroll
            for (int mf = 0; mf < 4; mf++)
                LDSM4(af[mf][0], af[mf][1], af[mf][2], af[mf][3], aaddr + mf * 1024);
            #pragma unroll
            for (int nb = 0; nb < 2; nb++)
                LDSM4(br[nb][0], br[nb][1], br[nb][2], br[nb][3], baddr + nb * 1024);
            #pragma unroll
            for (int mf = 0; mf < 4; mf++) {
                #pragma unroll
                for (int nf = 0; nf < 4; nf++) {
                    uint32_t b2[2] = { br[nf >> 1][nf & 1], br[nf >> 1][(nf & 1) + 2] };
                    mma16(acc[mf][nf], af[mf], b2);
                }
            }
        }
        if (it + 2 < NIT) {
            int s2 = s + 2; if (s2 >= 3) s2 -= 3;
            const int k0 = (it + 2) << 5;
            cpa16(sA + s2 * STGB + o0, Ag0 + k0);
            cpa16(sA + s2 * STGB + o1, Ag1 + k0);
            cpa16(sB + s2 * STGB + o0, Bg0 + k0);
            cpa16(sB + s2 * STGB + o1, Bg1 + k0);
        }
        CP_COMMIT();
        CP_WAIT1();
        __syncthreads();
        if (++s == 3) s = 0;
    }
}

// ---------------- epilogue helpers ----------------
#define EPI_NONE 0
#define EPI_TANH 1
#define EPI_W    2
#define EPI_SIG  3
#define EPI_VMIX 4

__device__ __forceinline__ void zero_acc(float acc[4][4][4]) {
    #pragma unroll
    for (int i = 0; i < 4; i++)
        #pragma unroll
        for (int j = 0; j < 4; j++)
            #pragma unroll
            for (int q = 0; q < 4; q++) acc[i][j][q] = 0.0f;
}

// ---------------- big-3 GEMMs (z-merged) ----------------
__global__ __launch_bounds__(256, 2) void gemm_big3(float* __restrict__ out_r)
{
    __shared__ __half smA[3 * STGB / 2];
    __shared__ __half smB[3 * STGB / 2];
    const int z = blockIdx.z;
    const __half* A  = (z == 0) ? g_xr : (z == 1) ? g_xk : g_xv;
    const __half* Wp = (z == 0) ? g_wr : (z == 1) ? g_wk : g_wv;
    float* O         = (z == 0) ? out_r : (z == 1) ? g_ko : g_vg;

    const int n0 = blockIdx.x * 128;
    const int m0 = blockIdx.y * 128;
    float acc[4][4][4];
    zero_acc(acc);
    mainloop(A, Wp, Cdim, m0, n0, smem_u32(smA), smem_u32(smB), acc);

    const int lane = threadIdx.x & 31;
    const int wid  = threadIdx.x >> 5;
    const int wm = (wid >> 2) * 64, wn = (wid & 3) * 32;
    const int tq = lane >> 2, tr = lane & 3;
    #pragma unroll
    for (int mf = 0; mf < 4; mf++) {
        #pragma unroll
        for (int nf = 0; nf < 4; nf++) {
            const int n = n0 + wn + nf * 8 + tr * 2;
            #pragma unroll
            for (int h = 0; h < 2; h++) {
                const int m = m0 + wm + mf * 16 + tq + h * 8;
                *(float2*)&O[(size_t)m * Cdim + n] =
                    make_float2(acc[mf][nf][h * 2], acc[mf][nf][h * 2 + 1]);
            }
        }
    }
}

// ---------------- LoRA stage-1 (z-merged, half outputs) ----------------
__global__ __launch_bounds__(256, 2) void gemm_s1(void)
{
    __shared__ __half smA[3 * STGB / 2];
    __shared__ __half smB[3 * STGB / 2];
    const int z = blockIdx.z;
    const __half* A;
    const __half* Wp;
    __half* Oh;
    int N, epi;
    if (z == 0)      { A = g_xw; Wp = g_w1p; Oh = g_hw; N = 128; epi = EPI_TANH; }
    else if (z == 1) { A = g_xa; Wp = g_a1p; Oh = g_ha; N = 128; epi = EPI_NONE; }
    else if (z == 2) { A = g_xv; Wp = g_v1p; Oh = g_hv; N = 128; epi = EPI_NONE; }
    else             { A = g_xg; Wp = g_g1p; Oh = g_hg; N = 256; epi = EPI_SIG; }

    const int n0 = blockIdx.x * 128;
    const int m0 = blockIdx.y * 128;
    if (n0 >= N) return;

    float acc[4][4][4];
    zero_acc(acc);
    mainloop(A, Wp, Cdim, m0, n0, smem_u32(smA), smem_u32(smB), acc);

    const int lane = threadIdx.x & 31;
    const int wid  = threadIdx.x >> 5;
    const int wm = (wid >> 2) * 64, wn = (wid & 3) * 32;
    const int tq = lane >> 2, tr = lane & 3;
    #pragma unroll
    for (int mf = 0; mf < 4; mf++) {
        #pragma unroll
        for (int nf = 0; nf < 4; nf++) {
            const int n = n0 + wn + nf * 8 + tr * 2;
            #pragma unroll
            for (int h = 0; h < 2; h++) {
                const int m = m0 + wm + mf * 16 + tq + h * 8;
                float o0 = acc[mf][nf][h * 2], o1 = acc[mf][nf][h * 2 + 1];
                if (epi == EPI_TANH)     { o0 = tanhf(o0); o1 = tanhf(o1); }
                else if (epi == EPI_SIG) { o0 = sigmoidf_(o0); o1 = sigmoidf_(o1); }
                *(__half2*)&Oh[(size_t)m * N + n] = __floats2half2_rn(o0, o1);
            }
        }
    }
}

// ---------------- LoRA stage-2 (z-merged, fused epilogues) ----------------
__global__ __launch_bounds__(256, 2) void gemm_s2(
    float* __restrict__ out_w, float* __restrict__ out_a,
    float* __restrict__ out_v, float* __restrict__ out_g,
    const float* __restrict__ w0, const float* __restrict__ a0,
    const float* __restrict__ v0, const float* __restrict__ vfp)
{
    __shared__ __half smA[3 * STGB / 2];
    __shared__ __half smB[3 * STGB / 2];
    const int z = blockIdx.z;
    const __half* A;
    const __half* Wp;
    float* O;
    const float* bias = nullptr;
    int K, epi;
    if (z == 0)      { A = g_hw; Wp = g_w2p; O = out_w; K = 128; epi = EPI_W;    bias = w0; }
    else if (z == 1) { A = g_ha; Wp = g_a2p; O = out_a; K = 128; epi = EPI_SIG;  bias = a0; }
    else if (z == 2) { A = g_hv; Wp = g_v2p; O = out_v; K = 128; epi = EPI_VMIX; bias = v0; }
    else             { A = g_hg; Wp = g_g2p; O = out_g; K = 256; epi = EPI_NONE; }

    const int n0 = blockIdx.x * 128;
    const int m0 = blockIdx.y * 128;
    float acc[4][4][4];
    zero_acc(acc);
    mainloop(A, Wp, K, m0, n0, smem_u32(smA), smem_u32(smB), acc);

    const int lane = threadIdx.x & 31;
    const int wid  = threadIdx.x >> 5;
    const int wm = (wid >> 2) * 64, wn = (wid & 3) * 32;
    const int tq = lane >> 2, tr = lane & 3;
    #pragma unroll
    for (int mf = 0; mf < 4; mf++) {
        #pragma unroll
        for (int nf = 0; nf < 4; nf++) {
            const int n = n0 + wn + nf * 8 + tr * 2;
            float bv0 = 0.0f, bv1 = 0.0f;
            if (bias) { bv0 = bias[n]; bv1 = bias[n + 1]; }
            #pragma unroll
            for (int h = 0; h < 2; h++) {
                const int m = m0 + wm + mf * 16 + tq + h * 8;
                float v0c = acc[mf][nf][h * 2], v1c = acc[mf][nf][h * 2 + 1];
                float o0, o1;
                if (epi == EPI_W) {
                    float y0 = bv0 + v0c, y1 = bv1 + v1c;
                    o0 = -(fmaxf(-y0, 0.0f) + log1pf(expf(-fabsf(y0)))) - 0.5f;
                    o1 = -(fmaxf(-y1, 0.0f) + log1pf(expf(-fabsf(y1)))) - 0.5f;
                } else if (epi == EPI_SIG) {
                    o0 = sigmoidf_(v0c + bv0); o1 = sigmoidf_(v1c + bv1);
                } else if (epi == EPI_VMIX) {
                    float s0 = sigmoidf_(bv0 + v0c), s1 = sigmoidf_(bv1 + v1c);
                    size_t ix = (size_t)m * Cdim + n;
                    float vg0 = g_vg[ix], vg1 = g_vg[ix + 1];
                    o0 = vg0 + (vfp[ix] - vg0) * s0;
                    o1 = vg1 + (vfp[ix + 1] - vg1) * s1;
                } else { o0 = v0c; o1 = v1c; }
                *(float2*)&O[(size_t)m * Cdim + n] = make_float2(o0, o1);
            }
        }
    }
}

// ---------------- elementwise producers ----------------
__global__ __launch_bounds__(256) void mix_kernel(
    const float* __restrict__ x, const float* __restrict__ vf,
    const float* __restrict__ mr, const float* __restrict__ mw,
    const float* __restrict__ mk, const float* __restrict__ mv,
    const float* __restrict__ ma, const float* __restrict__ mg,
    float* __restrict__ out_vf)
{
    size_t idx = (size_t)blockIdx.x * blockDim.x + threadIdx.x;
    if (idx >= BTC) return;
    int c   = (int)(idx & (Cdim - 1));
    int row = (int)(idx >> 11);
    int t   = row & (Tdim - 1);
    float xc = x[idx];
    float xp = (t == 0) ? 0.0f : x[idx - Cdim];
    float xx = xp - xc;
    g_xr[idx] = __float2half(fmaf(xx, mr[c], xc));
    g_xw[idx] = __float2half(fmaf(xx, mw[c], xc));
    g_xk[idx] = __float2half(fmaf(xx, mk[c], xc));
    g_xv[idx] = __float2half(fmaf(xx, mv[c], xc));
    g_xa[idx] = __float2half(fmaf(xx, ma[c], xc));
    g_xg[idx] = __float2half(fmaf(xx, mg[c], xc));
    out_vf[idx] = vf[idx];
}

__global__ __launch_bounds__(256) void prep_big(
    const float* __restrict__ Wr, const float* __restrict__ Wk, const float* __restrict__ Wv)
{
    size_t idx = (size_t)blockIdx.x * blockDim.x + threadIdx.x;
    if (idx >= (size_t)Cdim * Cdim) return;
    int z = blockIdx.z;
    const float* W = (z == 0) ? Wr : (z == 1) ? Wk : Wv;
    __half* P = (z == 0) ? g_wr : (z == 1) ? g_wk : g_wv;
    P[idx] = __float2half(W[idx]);
}
__global__ __launch_bounds__(256) void prep_l1(const float* __restrict__ w1, __half* __restrict__ p, int D_, int Dp)
{
    size_t idx = (size_t)blockIdx.x * blockDim.x + threadIdx.x;
    if (idx >= (size_t)Dp * Cdim) return;
    int nn = (int)(idx / Cdim), k = (int)(idx % Cdim);
    p[idx] = __float2half((nn < D_) ? w1[(size_t)k * D_ + nn] : 0.0f);
}
__global__ __launch_bounds__(256) void prep_l2(const float* __restrict__ w2, __half* __restrict__ p, int D_, int Dp)
{
    size_t idx = (size_t)blockIdx.x * blockDim.x + threadIdx.x;
    if (idx >= (size_t)Cdim * Dp) return;
    int nn = (int)(idx / Dp), d = (int)(idx % Dp);
    p[idx] = __float2half((d < D_) ? w2[(size_t)d * Cdim + nn] : 0.0f);
}

// ---------------- kk / final k ----------------
__global__ __launch_bounds__(256) void kk_fin_kernel(
    const float* __restrict__ k_k, const float* __restrict__ k_a,
    const float* __restrict__ a_out,
    float* __restrict__ out_kk, float* __restrict__ out_k)
{
    int gw   = (blockIdx.x * blockDim.x + threadIdx.x) >> 5;
    int lane = threadIdx.x & 31;
    int row  = gw >> 5;
    int h    = gw & 31;
    if (row >= Mrows) return;
    int bse = row * Cdim + h * HSZ;
    int c0 = h * HSZ + lane, c1 = c0 + 32;
    float k0v = g_ko[bse + lane];
    float k1v = g_ko[bse + 32 + lane];
    float kk0 = k0v * k_k[c0];
    float kk1 = k1v * k_k[c1];
    float ss = kk0 * kk0 + kk1 * kk1;
    #pragma unroll
    for (int o = 16; o > 0; o >>= 1) ss += __shfl_xor_sync(0xFFFFFFFFu, ss, o);
    float inv = 1.0f / fmaxf(sqrtf(ss), 1e-12f);
    out_kk[bse + lane]      = kk0 * inv;
    out_kk[bse + 32 + lane] = kk1 * inv;
    float a0v = a_out[bse + lane];
    float a1v = a_out[bse + 32 + lane];
    out_k[bse + lane]      = k0v * fmaf(a0v - 1.0f, k_a[c0], 1.0f);
    out_k[bse + 32 + lane] = k1v * fmaf(a1v - 1.0f, k_a[c1], 1.0f);
}

// ---------------- launch ----------------
template <typename T>
static T* sym(const void* s) { void* p; cudaGetSymbolAddress(&p, s); return (T*)p; }

extern "C" void kernel_launch(void* const* d_in, const int* in_sizes, int n_in,
                              void* d_out, int out_size)
{
    const float* x   = (const float*)d_in[0];
    const float* vf  = (const float*)d_in[1];
    const float* x_r = (const float*)d_in[2];
    const float* x_w = (const float*)d_in[3];
    const float* x_k = (const float*)d_in[4];
    const float* x_v = (const float*)d_in[5];
    const float* x_a = (const float*)d_in[6];
    const float* x_g = (const float*)d_in[7];
    const float* w0  = (const float*)d_in[8];
    const float* w1  = (const float*)d_in[9];
    const float* w2  = (const float*)d_in[10];
    const float* a0  = (const float*)d_in[11];
    const float* a1  = (const float*)d_in[12];
    const float* a2  = (const float*)d_in[13];
    const float* v0  = (const float*)d_in[14];
    const float* v1  = (const float*)d_in[15];
    const float* v2  = (const float*)d_in[16];
    const float* g1  = (const float*)d_in[17];
    const float* g2  = (const float*)d_in[18];
    const float* k_k = (const float*)d_in[19];
    const float* k_a = (const float*)d_in[20];
    const float* Wr  = (const float*)d_in[21];
    const float* Wk  = (const float*)d_in[22];
    const float* Wv  = (const float*)d_in[23];
    (void)in_sizes; (void)n_in; (void)out_size;

    float* out = (float*)d_out;
    float* out_r  = out + 0 * BTC;
    float* out_w  = out + 1 * BTC;
    float* out_k  = out + 2 * BTC;
    float* out_v  = out + 3 * BTC;
    float* out_a  = out + 4 * BTC;
    float* out_g  = out + 5 * BTC;
    float* out_kk = out + 6 * BTC;
    float* out_vf = out + 7 * BTC;

    __half* p_w1 = sym<__half>(&g_w1p); __half* p_a1 = sym<__half>(&g_a1p);
    __half* p_v1 = sym<__half>(&g_v1p); __half* p_g1 = sym<__half>(&g_g1p);
    __half* p_w2 = sym<__half>(&g_w2p); __half* p_a2 = sym<__half>(&g_a2p);
    __half* p_v2 = sym<__half>(&g_v2p); __half* p_g2 = sym<__half>(&g_g2p);

    // 1. mix (fp16 activations) + vf copy
    mix_kernel<<<(int)((BTC + 255) / 256), 256>>>(x, vf, x_r, x_w, x_k, x_v, x_a, x_g, out_vf);

    // 2. weight preps
    prep_big<<<dim3((unsigned)(((size_t)Cdim * Cdim + 255) / 256), 1, 3), 256>>>(Wr, Wk, Wv);
    prep_l1<<<(128 * Cdim + 255) / 256, 256>>>(w1, p_w1, 128, 128);
    prep_l1<<<(128 * Cdim + 255) / 256, 256>>>(a1, p_a1, 128, 128);
    prep_l1<<<(128 * Cdim + 255) / 256, 256>>>(v1, p_v1, 64, 128);
    prep_l1<<<(256 * Cdim + 255) / 256, 256>>>(g1, p_g1, 224, 256);
    prep_l2<<<(Cdim * 128 + 255) / 256, 256>>>(w2, p_w2, 128, 128);
    prep_l2<<<(Cdim * 128 + 255) / 256, 256>>>(a2, p_a2, 128, 128);
    prep_l2<<<(Cdim * 128 + 255) / 256, 256>>>(v2, p_v2, 64, 128);
    prep_l2<<<(Cdim * 256 + 255) / 256, 256>>>(g2, p_g2, 224, 256);

    // 3. big GEMMs (merged)
    gemm_big3<<<dim3(Cdim / 128, Mrows / 128, 3), 256>>>(out_r);

    // 4. LoRA stage 1 (merged)
    gemm_s1<<<dim3(2, Mrows / 128, 4), 256>>>();

    // 5. LoRA stage 2 (merged, fused epilogues)
    gemm_s2<<<dim3(Cdim / 128, Mrows / 128, 4), 256>>>(out_w, out_a, out_v, out_g, w0, a0, v0, vf);

    // 6. kk normalize + final k
    kk_fin_kernel<<<Mrows * 32 * 32 / 256, 256>>>(k_k, k_a, out_a, out_kk, out_k);
}